// round 3
// baseline (speedup 1.0000x reference)
#include <cuda_runtime.h>
#include <cuda_bf16.h>
#include <math.h>
#include <stdint.h>

#define B_   2
#define T_   2048
#define C_   768
#define H_   12
#define DH_  64
#define LOG2E 1.4426950408889634f
#define SKU  12   // u32 stride per 16-k-chunk row (8 data + 4 pad) -> conflict-free frag LDS

// Scratch (device globals — no allocation allowed)
__device__ float g_q[B_ * T_ * C_];
__device__ float g_k[B_ * T_ * C_];
__device__ float g_v[B_ * T_ * C_];
__device__ float g_att[B_ * T_ * C_];
__device__ float2 g_stats[B_ * H_ * T_];   // per row: (max, 1/sum_exp)

// ---------------------------------------------------------------------------
// bf16 split helpers: v = hi + lo with hi,lo bf16 (residual ~2^-18 rel)
// ---------------------------------------------------------------------------
__device__ __forceinline__ void split1(float v, __nv_bfloat16& h, __nv_bfloat16& l) {
    h = __float2bfloat16(v);
    l = __float2bfloat16(v - __bfloat162float(h));
}
__device__ __forceinline__ void split2(float v0, float v1, uint32_t& hi, uint32_t& lo) {
    __nv_bfloat16 h0, l0, h1, l1;
    split1(v0, h0, l0);
    split1(v1, h1, l1);
    hi = ((uint32_t)__bfloat16_as_ushort(h1) << 16) | (uint32_t)__bfloat16_as_ushort(h0);
    lo = ((uint32_t)__bfloat16_as_ushort(l1) << 16) | (uint32_t)__bfloat16_as_ushort(l0);
}

__device__ __forceinline__ void mma16(float4& d, const uint32_t* a, const uint32_t* b) {
    asm("mma.sync.aligned.m16n8k16.row.col.f32.bf16.bf16.f32 "
        "{%0,%1,%2,%3}, {%4,%5,%6,%7}, {%8,%9}, {%0,%1,%2,%3};"
        : "+f"(d.x), "+f"(d.y), "+f"(d.z), "+f"(d.w)
        : "r"(a[0]), "r"(a[1]), "r"(a[2]), "r"(a[3]), "r"(b[0]), "r"(b[1]));
}

// Load [128 rows x 16 k] fp32 tile (row stride ld) into hi/lo bf16-pair smem.
__device__ __forceinline__ void load_tile_bf16(const float* __restrict__ src, int ld,
                                               uint32_t (*Sh)[SKU], uint32_t (*Sl)[SKU],
                                               int tid) {
#pragma unroll
    for (int it = 0; it < 2; it++) {
        int idx = tid + it * 256;          // 512 float4s
        int row = idx >> 2;
        int ko  = (idx & 3) << 2;
        float4 v = *(const float4*)(src + (size_t)row * ld + ko);
        uint32_t h0, l0, h1, l1;
        split2(v.x, v.y, h0, l0);
        split2(v.z, v.w, h1, l1);
        int c0 = ko >> 1;
        Sh[row][c0] = h0; Sh[row][c0 + 1] = h1;
        Sl[row][c0] = l0; Sl[row][c0 + 1] = l1;
    }
}

// ---------------------------------------------------------------------------
// NT GEMM via bf16 2-split (3 MMA products).
// C[m,n] = alpha * sum_k A[m*lda+k]*B[n*ldb+k].  M%128==0, N%128==0, K%16==0.
// ---------------------------------------------------------------------------
__global__ void __launch_bounds__(256) gemm_nt_tc(const float* __restrict__ A,
                                                  const float* __restrict__ Bm,
                                                  float* __restrict__ C,
                                                  int K, int lda, int ldb, int ldc,
                                                  float alpha) {
    __shared__ uint32_t Ah[128][SKU], Al[128][SKU], Bh[128][SKU], Bl[128][SKU];
    const int tid = threadIdx.x;
    const int m0 = blockIdx.y * 128, n0 = blockIdx.x * 128;
    const int warp = tid >> 5, lane = tid & 31;
    const int wm = (warp >> 2) * 64, wn = (warp & 3) * 32;
    const int r = lane >> 2, c = lane & 3;

    float4 acc[4][4];
#pragma unroll
    for (int i = 0; i < 4; i++)
#pragma unroll
        for (int j = 0; j < 4; j++) acc[i][j] = make_float4(0, 0, 0, 0);

    for (int k0 = 0; k0 < K; k0 += 16) {
        __syncthreads();
        load_tile_bf16(A + (size_t)m0 * lda + k0, lda, Ah, Al, tid);
        load_tile_bf16(Bm + (size_t)n0 * ldb + k0, ldb, Bh, Bl, tid);
        __syncthreads();
        uint32_t bh[4][2], bl[4][2];
#pragma unroll
        for (int nj = 0; nj < 4; nj++) {
            int col = wn + nj * 8 + r;
            bh[nj][0] = Bh[col][c]; bh[nj][1] = Bh[col][c + 4];
            bl[nj][0] = Bl[col][c]; bl[nj][1] = Bl[col][c + 4];
        }
#pragma unroll
        for (int mi = 0; mi < 4; mi++) {
            int row = wm + mi * 16 + r;
            uint32_t ah[4] = {Ah[row][c], Ah[row + 8][c], Ah[row][c + 4], Ah[row + 8][c + 4]};
            uint32_t al[4] = {Al[row][c], Al[row + 8][c], Al[row][c + 4], Al[row + 8][c + 4]};
#pragma unroll
            for (int nj = 0; nj < 4; nj++) {
                mma16(acc[mi][nj], al, bh[nj]);
                mma16(acc[mi][nj], ah, bl[nj]);
                mma16(acc[mi][nj], ah, bh[nj]);
            }
        }
    }
#pragma unroll
    for (int mi = 0; mi < 4; mi++)
#pragma unroll
        for (int nj = 0; nj < 4; nj++) {
            int gm = m0 + wm + mi * 16 + r;
            int gn = n0 + wn + nj * 8 + 2 * c;
            *(float2*)&C[(size_t)gm * ldc + gn] =
                make_float2(alpha * acc[mi][nj].x, alpha * acc[mi][nj].y);
            *(float2*)&C[(size_t)(gm + 8) * ldc + gn] =
                make_float2(alpha * acc[mi][nj].z, alpha * acc[mi][nj].w);
        }
}

// ---------------------------------------------------------------------------
// Raw scaled scores: S = 0.125 * Q.K^T, masked entries -> 0, zero tiles filled.
// grid (16, 16, 24)
// ---------------------------------------------------------------------------
__global__ void __launch_bounds__(256) scores_tc(const float* __restrict__ Q,
                                                 const float* __restrict__ Kt,
                                                 float* __restrict__ W) {
    const int z = blockIdx.z;
    const int b = z / H_, h = z % H_;
    const int m0 = blockIdx.y * 128, n0 = blockIdx.x * 128;
    const int tid = threadIdx.x;
    float* Cz = W + (size_t)z * T_ * T_;

    if (n0 > m0) {  // fully masked tile -> zeros
        const float4 zz = make_float4(0, 0, 0, 0);
        for (int idx = tid; idx < 128 * 32; idx += 256) {
            int row = idx >> 5, c4 = (idx & 31) << 2;
            *(float4*)&Cz[(size_t)(m0 + row) * T_ + n0 + c4] = zz;
        }
        return;
    }

    __shared__ uint32_t Ah[128][SKU], Al[128][SKU], Bh[128][SKU], Bl[128][SKU];
    const int warp = tid >> 5, lane = tid & 31;
    const int wm = (warp >> 2) * 64, wn = (warp & 3) * 32;
    const int r = lane >> 2, c = lane & 3;
    const float* Ap = Q + (size_t)b * T_ * C_ + h * DH_;
    const float* Bp = Kt + (size_t)b * T_ * C_ + h * DH_;

    float4 acc[4][4];
#pragma unroll
    for (int i = 0; i < 4; i++)
#pragma unroll
        for (int j = 0; j < 4; j++) acc[i][j] = make_float4(0, 0, 0, 0);

#pragma unroll
    for (int k0 = 0; k0 < DH_; k0 += 16) {
        __syncthreads();
        load_tile_bf16(Ap + (size_t)m0 * C_ + k0, C_, Ah, Al, tid);
        load_tile_bf16(Bp + (size_t)n0 * C_ + k0, C_, Bh, Bl, tid);
        __syncthreads();
        uint32_t bh[4][2], bl[4][2];
#pragma unroll
        for (int nj = 0; nj < 4; nj++) {
            int col = wn + nj * 8 + r;
            bh[nj][0] = Bh[col][c]; bh[nj][1] = Bh[col][c + 4];
            bl[nj][0] = Bl[col][c]; bl[nj][1] = Bl[col][c + 4];
        }
#pragma unroll
        for (int mi = 0; mi < 4; mi++) {
            int row = wm + mi * 16 + r;
            uint32_t ah[4] = {Ah[row][c], Ah[row + 8][c], Ah[row][c + 4], Ah[row + 8][c + 4]};
            uint32_t al[4] = {Al[row][c], Al[row + 8][c], Al[row][c + 4], Al[row + 8][c + 4]};
#pragma unroll
            for (int nj = 0; nj < 4; nj++) {
                mma16(acc[mi][nj], al, bh[nj]);
                mma16(acc[mi][nj], ah, bl[nj]);
                mma16(acc[mi][nj], ah, bh[nj]);
            }
        }
    }

    const bool diag = (n0 == m0);
#pragma unroll
    for (int mi = 0; mi < 4; mi++)
#pragma unroll
        for (int nj = 0; nj < 4; nj++) {
            int gm = m0 + wm + mi * 16 + r;
            int gn = n0 + wn + nj * 8 + 2 * c;
            float x0 = 0.125f * acc[mi][nj].x, y0 = 0.125f * acc[mi][nj].y;
            float z1 = 0.125f * acc[mi][nj].z, w1 = 0.125f * acc[mi][nj].w;
            if (diag) {
                if (gn > gm) x0 = 0.0f;
                if (gn + 1 > gm) y0 = 0.0f;
                if (gn > gm + 8) z1 = 0.0f;
                if (gn + 1 > gm + 8) w1 = 0.0f;
            }
            *(float2*)&Cz[(size_t)gm * T_ + gn]       = make_float2(x0, y0);
            *(float2*)&Cz[(size_t)(gm + 8) * T_ + gn] = make_float2(z1, w1);
        }
}

// ---------------------------------------------------------------------------
// Row stats: m = max over valid prefix, il = 1/sum(exp(s-m)). One block/row.
// ---------------------------------------------------------------------------
__global__ void __launch_bounds__(256) stats_kernel(const float* __restrict__ W,
                                                    float2* __restrict__ stats) {
    const int rrow = blockIdx.x;          // [0, B*H*T)
    const int i = rrow % T_;
    const int valid = i + 1;
    const float* row = W + (size_t)rrow * T_;

    __shared__ float buf[T_];
    __shared__ float warpred[8];
    const int tid = threadIdx.x;

    float mx = -1e30f;
    for (int j = tid; j < valid; j += 256) {
        float v = row[j];
        buf[j] = v;
        mx = fmaxf(mx, v);
    }
#pragma unroll
    for (int o = 16; o; o >>= 1) mx = fmaxf(mx, __shfl_xor_sync(0xffffffffu, mx, o));
    if ((tid & 31) == 0) warpred[tid >> 5] = mx;
    __syncthreads();
    mx = warpred[0];
#pragma unroll
    for (int w = 1; w < 8; w++) mx = fmaxf(mx, warpred[w]);

    float sm = 0.0f;
    for (int j = tid; j < valid; j += 256)
        sm += exp2f((buf[j] - mx) * LOG2E);
#pragma unroll
    for (int o = 16; o; o >>= 1) sm += __shfl_xor_sync(0xffffffffu, sm, o);
    __syncthreads();
    if ((tid & 31) == 0) warpred[tid >> 5] = sm;
    __syncthreads();
    if (tid == 0) {
        float s = 0.0f;
#pragma unroll
        for (int w = 0; w < 8; w++) s += warpred[w];
        stats[rrow] = make_float2(mx, 1.0f / s);
    }
}

// ---------------------------------------------------------------------------
// Fused normalize + weights-write + PV:
//   reads raw scores, w = exp(s-m)*il (masked->0), writes w (weights output),
//   accumulates O = w @ V. grid (1, 16, 24).
// ---------------------------------------------------------------------------
__global__ void __launch_bounds__(256) pv_norm_tc(float* __restrict__ W,
                                                  const float* __restrict__ V,
                                                  float* __restrict__ O,
                                                  const float2* __restrict__ stats) {
    const int z = blockIdx.z;
    const int b = z / H_, h = z % H_;
    const int m0 = blockIdx.y * 128;
    const int tid = threadIdx.x;
    const int warp = tid >> 5, lane = tid & 31;
    const int wm = (warp >> 2) * 64, wn = (warp & 3) * 16;
    const int r = lane >> 2, c = lane & 3;

    float* Wz = W + (size_t)z * T_ * T_;
    const float* Vp = V + (size_t)b * T_ * C_ + h * DH_;   // V[k][n], stride C_

    __shared__ uint32_t Ah[128][SKU], Al[128][SKU];
    __shared__ __nv_bfloat16 Bh16[64][2 * SKU], Bl16[64][2 * SKU];
    __shared__ float m_s[128], il_s[128];

    if (tid < 128) {
        float2 st = stats[z * T_ + m0 + tid];
        m_s[tid] = st.x;
        il_s[tid] = st.y;
    }

    float4 acc[4][2];
#pragma unroll
    for (int i = 0; i < 4; i++)
#pragma unroll
        for (int j = 0; j < 2; j++) acc[i][j] = make_float4(0, 0, 0, 0);

    const int kmax = m0 + 128;
    for (int k0 = 0; k0 < kmax; k0 += 16) {
        __syncthreads();
        // A tile = normalized weights (computed from raw scores), 128 x 16
#pragma unroll
        for (int it = 0; it < 2; it++) {
            int idx = tid + it * 256;
            int row = idx >> 2;
            int ko  = (idx & 3) << 2;
            float* addr = &Wz[(size_t)(m0 + row) * T_ + k0 + ko];
            float4 v = *(const float4*)addr;
            const int gm = m0 + row, gc = k0 + ko;
            const float mrow = m_s[row], il = il_s[row];
            float w0 = (gc     <= gm) ? exp2f((v.x - mrow) * LOG2E) * il : 0.0f;
            float w1 = (gc + 1 <= gm) ? exp2f((v.y - mrow) * LOG2E) * il : 0.0f;
            float w2 = (gc + 2 <= gm) ? exp2f((v.z - mrow) * LOG2E) * il : 0.0f;
            float w3 = (gc + 3 <= gm) ? exp2f((v.w - mrow) * LOG2E) * il : 0.0f;
            *(float4*)addr = make_float4(w0, w1, w2, w3);   // weights output
            uint32_t h0, l0, h1, l1;
            split2(w0, w1, h0, l0);
            split2(w2, w3, h1, l1);
            int c0 = ko >> 1;
            Ah[row][c0] = h0; Ah[row][c0 + 1] = h1;
            Al[row][c0] = l0; Al[row][c0 + 1] = l1;
        }
        // B tile: Bs[n][k] = V[k0+k][n]
        {
            int kr = tid >> 4;            // 0..15
            int nc = (tid & 15) << 2;     // 0..60
            float4 v = *(const float4*)(Vp + (size_t)(k0 + kr) * C_ + nc);
            __nv_bfloat16 hh, ll;
            split1(v.x, hh, ll); Bh16[nc + 0][kr] = hh; Bl16[nc + 0][kr] = ll;
            split1(v.y, hh, ll); Bh16[nc + 1][kr] = hh; Bl16[nc + 1][kr] = ll;
            split1(v.z, hh, ll); Bh16[nc + 2][kr] = hh; Bl16[nc + 2][kr] = ll;
            split1(v.w, hh, ll); Bh16[nc + 3][kr] = hh; Bl16[nc + 3][kr] = ll;
        }
        __syncthreads();
        uint32_t bh[2][2], bl[2][2];
#pragma unroll
        for (int nj = 0; nj < 2; nj++) {
            int col = wn + nj * 8 + r;
            const uint32_t* ph = (const uint32_t*)&Bh16[col][0];
            const uint32_t* pl = (const uint32_t*)&Bl16[col][0];
            bh[nj][0] = ph[c]; bh[nj][1] = ph[c + 4];
            bl[nj][0] = pl[c]; bl[nj][1] = pl[c + 4];
        }
#pragma unroll
        for (int mi = 0; mi < 4; mi++) {
            int row = wm + mi * 16 + r;
            uint32_t ah[4] = {Ah[row][c], Ah[row + 8][c], Ah[row][c + 4], Ah[row + 8][c + 4]};
            uint32_t al[4] = {Al[row][c], Al[row + 8][c], Al[row][c + 4], Al[row + 8][c + 4]};
#pragma unroll
            for (int nj = 0; nj < 2; nj++) {
                mma16(acc[mi][nj], al, bh[nj]);
                mma16(acc[mi][nj], ah, bl[nj]);
                mma16(acc[mi][nj], ah, bh[nj]);
            }
        }
    }
#pragma unroll
    for (int mi = 0; mi < 4; mi++)
#pragma unroll
        for (int nj = 0; nj < 2; nj++) {
            int gm = m0 + wm + mi * 16 + r;
            int gn = wn + nj * 8 + 2 * c;
            *(float2*)&O[(size_t)(b * T_ + gm) * C_ + h * DH_ + gn] =
                make_float2(acc[mi][nj].x, acc[mi][nj].y);
            *(float2*)&O[(size_t)(b * T_ + gm + 8) * C_ + h * DH_ + gn] =
                make_float2(acc[mi][nj].z, acc[mi][nj].w);
        }
}

// ---------------------------------------------------------------------------
extern "C" void kernel_launch(void* const* d_in, const int* in_sizes, int n_in,
                              void* d_out, int out_size) {
    const float* x   = (const float*)d_in[0];
    const float* w_q = (const float*)d_in[1];
    const float* w_k = (const float*)d_in[2];
    const float* w_v = (const float*)d_in[3];
    const float* w_o = (const float*)d_in[4];

    float* qp; cudaGetSymbolAddress((void**)&qp, g_q);
    float* kp; cudaGetSymbolAddress((void**)&kp, g_k);
    float* vp; cudaGetSymbolAddress((void**)&vp, g_v);
    float* ap; cudaGetSymbolAddress((void**)&ap, g_att);
    float2* sp; cudaGetSymbolAddress((void**)&sp, g_stats);

    float* final_out = (float*)d_out;                       // [B,T,C]
    float* w_out = (float*)d_out + (size_t)B_ * T_ * C_;    // [B,H,T,T]

    const dim3 blk(256);
    const dim3 gproj(C_ / 128, (B_ * T_) / 128);            // (6, 32)

    gemm_nt_tc<<<gproj, blk>>>(x, w_q, qp, C_, C_, C_, C_, 1.0f);
    gemm_nt_tc<<<gproj, blk>>>(x, w_k, kp, C_, C_, C_, C_, 1.0f);
    gemm_nt_tc<<<gproj, blk>>>(x, w_v, vp, C_, C_, C_, C_, 1.0f);

    scores_tc<<<dim3(T_ / 128, T_ / 128, B_ * H_), blk>>>(qp, kp, w_out);

    stats_kernel<<<B_ * H_ * T_, blk>>>(w_out, sp);

    pv_norm_tc<<<dim3(1, T_ / 128, B_ * H_), blk>>>(w_out, vp, ap, sp);

    gemm_nt_tc<<<gproj, blk>>>(ap, w_o, final_out, C_, C_, C_, C_, 1.0f);
}

// round 4
// speedup vs baseline: 1.2077x; 1.2077x over previous
#include <cuda_runtime.h>
#include <math.h>
#include <stdint.h>

#define B_   2
#define T_   2048
#define C_   768
#define H_   12
#define DH_  64
#define LOG2E 1.4426950408889634f
#define SK   20   // smem k-stride (16 data + 4 pad) -> conflict-free frag LDS

// Scratch (device globals — no allocation allowed)
__device__ float g_q[B_ * T_ * C_];
__device__ float g_k[B_ * T_ * C_];
__device__ float g_v[B_ * T_ * C_];
__device__ float g_att[B_ * T_ * C_];
__device__ float g_partial[B_ * H_ * T_ * 16];  // per (row, colTile) partial sum(exp)
__device__ float g_invsum[B_ * H_ * T_];        // per row: 1/sum(exp)

// ---------------------------------------------------------------------------
// tf32 helpers
// ---------------------------------------------------------------------------
__device__ __forceinline__ uint32_t f2tf(float v) {
    uint32_t r;
    asm("cvt.rna.tf32.f32 %0, %1;" : "=r"(r) : "f"(v));
    return r;
}

__device__ __forceinline__ void mma8(float4& d, const uint32_t* a, const uint32_t* b) {
    asm("mma.sync.aligned.m16n8k8.row.col.f32.tf32.tf32.f32 "
        "{%0,%1,%2,%3}, {%4,%5,%6,%7}, {%8,%9}, {%0,%1,%2,%3};"
        : "+f"(d.x), "+f"(d.y), "+f"(d.z), "+f"(d.w)
        : "r"(a[0]), "r"(a[1]), "r"(a[2]), "r"(a[3]), "r"(b[0]), "r"(b[1]));
}

// Load a [128 rows x 16 k] fp32 tile (row stride ld) into hi/lo tf32 smem.
__device__ __forceinline__ void load_tile128(const float* __restrict__ src, int ld,
                                             uint32_t (*Sh)[SK], uint32_t (*Sl)[SK],
                                             int tid) {
#pragma unroll
    for (int it = 0; it < 2; it++) {
        int idx = tid + it * 256;            // 512 float4s total
        int row = idx >> 2;
        int ko  = (idx & 3) << 2;
        float4 v = *(const float4*)(src + (size_t)row * ld + ko);
        uint32_t h;
        h = f2tf(v.x); Sh[row][ko + 0] = h; Sl[row][ko + 0] = f2tf(v.x - __uint_as_float(h));
        h = f2tf(v.y); Sh[row][ko + 1] = h; Sl[row][ko + 1] = f2tf(v.y - __uint_as_float(h));
        h = f2tf(v.z); Sh[row][ko + 2] = h; Sl[row][ko + 2] = f2tf(v.z - __uint_as_float(h));
        h = f2tf(v.w); Sh[row][ko + 3] = h; Sl[row][ko + 3] = f2tf(v.w - __uint_as_float(h));
    }
}

// ---------------------------------------------------------------------------
// Shared NT-GEMM body (3xTF32). C[m,n] = sum_k A[m*lda+k]*B[n*ldb+k]
// ---------------------------------------------------------------------------
__device__ __forceinline__ void gemm_body(const float* __restrict__ A,
                                          const float* __restrict__ Bm,
                                          float* __restrict__ C,
                                          int K, int lda, int ldb, int ldc,
                                          int m0, int n0) {
    __shared__ uint32_t Ah[128][SK], Al[128][SK], Bh[128][SK], Bl[128][SK];
    const int tid = threadIdx.x;
    const int warp = tid >> 5, lane = tid & 31;
    const int wm = (warp >> 2) * 64, wn = (warp & 3) * 32;
    const int r = lane >> 2, c = lane & 3;

    float4 acc[4][4];
#pragma unroll
    for (int i = 0; i < 4; i++)
#pragma unroll
        for (int j = 0; j < 4; j++) acc[i][j] = make_float4(0, 0, 0, 0);

    for (int k0 = 0; k0 < K; k0 += 16) {
        __syncthreads();
        load_tile128(A + (size_t)m0 * lda + k0, lda, Ah, Al, tid);
        load_tile128(Bm + (size_t)n0 * ldb + k0, ldb, Bh, Bl, tid);
        __syncthreads();
#pragma unroll
        for (int kb = 0; kb < 16; kb += 8) {
            uint32_t bh[4][2], bl[4][2];
#pragma unroll
            for (int nj = 0; nj < 4; nj++) {
                int col = wn + nj * 8 + r;
                bh[nj][0] = Bh[col][kb + c]; bh[nj][1] = Bh[col][kb + c + 4];
                bl[nj][0] = Bl[col][kb + c]; bl[nj][1] = Bl[col][kb + c + 4];
            }
#pragma unroll
            for (int mi = 0; mi < 4; mi++) {
                int row = wm + mi * 16 + r;
                uint32_t ah[4], al[4];
                ah[0] = Ah[row][kb + c];     ah[1] = Ah[row + 8][kb + c];
                ah[2] = Ah[row][kb + c + 4]; ah[3] = Ah[row + 8][kb + c + 4];
                al[0] = Al[row][kb + c];     al[1] = Al[row + 8][kb + c];
                al[2] = Al[row][kb + c + 4]; al[3] = Al[row + 8][kb + c + 4];
#pragma unroll
                for (int nj = 0; nj < 4; nj++) {
                    mma8(acc[mi][nj], al, bh[nj]);
                    mma8(acc[mi][nj], ah, bl[nj]);
                    mma8(acc[mi][nj], ah, bh[nj]);
                }
            }
        }
    }
#pragma unroll
    for (int mi = 0; mi < 4; mi++)
#pragma unroll
        for (int nj = 0; nj < 4; nj++) {
            int gm = m0 + wm + mi * 16 + r;
            int gn = n0 + wn + nj * 8 + 2 * c;
            *(float2*)&C[(size_t)gm * ldc + gn]       = make_float2(acc[mi][nj].x, acc[mi][nj].y);
            *(float2*)&C[(size_t)(gm + 8) * ldc + gn] = make_float2(acc[mi][nj].z, acc[mi][nj].w);
        }
}

// Fused QKV projection: grid (18, 32); x-blocks [0,6)->Q, [6,12)->K, [12,18)->V
__global__ void __launch_bounds__(256) gemm_qkv(const float* __restrict__ x,
                                                const float* __restrict__ wq,
                                                const float* __restrict__ wk,
                                                const float* __restrict__ wv,
                                                float* __restrict__ q,
                                                float* __restrict__ k,
                                                float* __restrict__ v) {
    const int nb = blockIdx.x;
    const int sel = nb / 6;
    const int n0 = (nb % 6) * 128;
    const int m0 = blockIdx.y * 128;
    const float* W = (sel == 0) ? wq : (sel == 1) ? wk : wv;
    float* O = (sel == 0) ? q : (sel == 1) ? k : v;
    gemm_body(x, W, O, C_, C_, C_, C_, m0, n0);
}

// Final projection: grid (6, 32)
__global__ void __launch_bounds__(256) gemm_final(const float* __restrict__ A,
                                                  const float* __restrict__ Wo,
                                                  float* __restrict__ C) {
    gemm_body(A, Wo, C, C_, C_, C_, C_, blockIdx.y * 128, blockIdx.x * 128);
}

// ---------------------------------------------------------------------------
// Scores + per-tile row partial sums of exp.
// S = 0.125*Q.K^T (masked->0). partial[(z*T+row)*16 + n0/128] = sum_j exp(S)
// grid (16, 16, 24)
// ---------------------------------------------------------------------------
__global__ void __launch_bounds__(256) scores_tc(const float* __restrict__ Q,
                                                 const float* __restrict__ Kt,
                                                 float* __restrict__ W,
                                                 float* __restrict__ partial) {
    const int z = blockIdx.z;
    const int b = z / H_, h = z % H_;
    const int m0 = blockIdx.y * 128, n0 = blockIdx.x * 128;
    const int tid = threadIdx.x;
    float* Cz = W + (size_t)z * T_ * T_;

    if (n0 > m0) {  // fully masked tile -> zeros; no partials
        const float4 zz = make_float4(0, 0, 0, 0);
        for (int idx = tid; idx < 128 * 32; idx += 256) {
            int row = idx >> 5, c4 = (idx & 31) << 2;
            *(float4*)&Cz[(size_t)(m0 + row) * T_ + n0 + c4] = zz;
        }
        return;
    }

    __shared__ uint32_t Ah[128][SK], Al[128][SK], Bh[128][SK], Bl[128][SK];
    __shared__ float spart[128][4];
    const int warp = tid >> 5, lane = tid & 31;
    const int wm = (warp >> 2) * 64, wn = (warp & 3) * 32;
    const int r = lane >> 2, c = lane & 3;
    const float* Ap = Q + (size_t)b * T_ * C_ + h * DH_;
    const float* Bp = Kt + (size_t)b * T_ * C_ + h * DH_;

    float4 acc[4][4];
#pragma unroll
    for (int i = 0; i < 4; i++)
#pragma unroll
        for (int j = 0; j < 4; j++) acc[i][j] = make_float4(0, 0, 0, 0);

#pragma unroll
    for (int k0 = 0; k0 < DH_; k0 += 16) {
        __syncthreads();
        load_tile128(Ap + (size_t)m0 * C_ + k0, C_, Ah, Al, tid);
        load_tile128(Bp + (size_t)n0 * C_ + k0, C_, Bh, Bl, tid);
        __syncthreads();
#pragma unroll
        for (int kb = 0; kb < 16; kb += 8) {
            uint32_t bh[4][2], bl[4][2];
#pragma unroll
            for (int nj = 0; nj < 4; nj++) {
                int col = wn + nj * 8 + r;
                bh[nj][0] = Bh[col][kb + c]; bh[nj][1] = Bh[col][kb + c + 4];
                bl[nj][0] = Bl[col][kb + c]; bl[nj][1] = Bl[col][kb + c + 4];
            }
#pragma unroll
            for (int mi = 0; mi < 4; mi++) {
                int row = wm + mi * 16 + r;
                uint32_t ah[4], al[4];
                ah[0] = Ah[row][kb + c];     ah[1] = Ah[row + 8][kb + c];
                ah[2] = Ah[row][kb + c + 4]; ah[3] = Ah[row + 8][kb + c + 4];
                al[0] = Al[row][kb + c];     al[1] = Al[row + 8][kb + c];
                al[2] = Al[row][kb + c + 4]; al[3] = Al[row + 8][kb + c + 4];
#pragma unroll
                for (int nj = 0; nj < 4; nj++) {
                    mma8(acc[mi][nj], al, bh[nj]);
                    mma8(acc[mi][nj], ah, bl[nj]);
                    mma8(acc[mi][nj], ah, bh[nj]);
                }
            }
        }
    }

    const bool diag = (n0 == m0);
#pragma unroll
    for (int mi = 0; mi < 4; mi++) {
        float se0 = 0.0f, se1 = 0.0f;   // exp-sums for rows gm and gm+8
        int gm = m0 + wm + mi * 16 + r;
#pragma unroll
        for (int nj = 0; nj < 4; nj++) {
            int gn = n0 + wn + nj * 8 + 2 * c;
            float x0 = 0.125f * acc[mi][nj].x, y0 = 0.125f * acc[mi][nj].y;
            float z1 = 0.125f * acc[mi][nj].z, w1 = 0.125f * acc[mi][nj].w;
            bool vx = true, vy = true, vz = true, vw = true;
            if (diag) {
                vx = (gn <= gm); vy = (gn + 1 <= gm);
                vz = (gn <= gm + 8); vw = (gn + 1 <= gm + 8);
                if (!vx) x0 = 0.0f;
                if (!vy) y0 = 0.0f;
                if (!vz) z1 = 0.0f;
                if (!vw) w1 = 0.0f;
            }
            se0 += (vx ? exp2f(x0 * LOG2E) : 0.0f) + (vy ? exp2f(y0 * LOG2E) : 0.0f);
            se1 += (vz ? exp2f(z1 * LOG2E) : 0.0f) + (vw ? exp2f(w1 * LOG2E) : 0.0f);
            *(float2*)&Cz[(size_t)gm * T_ + gn]       = make_float2(x0, y0);
            *(float2*)&Cz[(size_t)(gm + 8) * T_ + gn] = make_float2(z1, w1);
        }
        // reduce over the 4 c-lanes (lane bits 0-1)
        se0 += __shfl_xor_sync(0xffffffffu, se0, 1);
        se0 += __shfl_xor_sync(0xffffffffu, se0, 2);
        se1 += __shfl_xor_sync(0xffffffffu, se1, 1);
        se1 += __shfl_xor_sync(0xffffffffu, se1, 2);
        if (c == 0) {
            spart[wm + mi * 16 + r][warp & 3]     = se0;
            spart[wm + mi * 16 + r + 8][warp & 3] = se1;
        }
    }
    __syncthreads();
    if (tid < 128) {
        float s = spart[tid][0] + spart[tid][1] + spart[tid][2] + spart[tid][3];
        partial[((size_t)z * T_ + m0 + tid) * 16 + (n0 >> 7)] = s;
    }
}

// ---------------------------------------------------------------------------
// Reduce partials -> 1/rowsum. grid (B*H*T/256), 256 thr.
// ---------------------------------------------------------------------------
__global__ void __launch_bounds__(256) reduce_kernel(const float* __restrict__ partial,
                                                     float* __restrict__ invsum) {
    const int rg = blockIdx.x * 256 + threadIdx.x;   // [0, B*H*T)
    const int i = rg % T_;
    const int ntmax = i >> 7;
    float s = 0.0f;
    const float* p = partial + (size_t)rg * 16;
    for (int nt = 0; nt <= ntmax; nt++) s += p[nt];
    invsum[rg] = 1.0f / s;
}

// ---------------------------------------------------------------------------
// Fused normalize + weights-write + PV (3xTF32):
//   w = exp(s)*invsum (masked->0), write w, O = w @ V.
// grid (1, 16, 24), y reversed for wave balance.
// ---------------------------------------------------------------------------
__global__ void __launch_bounds__(256) pv_norm_tc(float* __restrict__ W,
                                                  const float* __restrict__ V,
                                                  float* __restrict__ O,
                                                  const float* __restrict__ invsum) {
    const int z = blockIdx.z;
    const int b = z / H_, h = z % H_;
    const int m0 = (gridDim.y - 1 - blockIdx.y) * 128;   // heavy blocks first
    const int tid = threadIdx.x;
    const int warp = tid >> 5, lane = tid & 31;
    const int wm = (warp >> 2) * 64, wn = (warp & 3) * 16;
    const int r = lane >> 2, c = lane & 3;

    float* Wz = W + (size_t)z * T_ * T_;
    const float* Vp = V + (size_t)b * T_ * C_ + h * DH_;   // V[k][n], stride C_

    __shared__ uint32_t Ah[128][SK], Al[128][SK], Bh[64][SK], Bl[64][SK];
    __shared__ float il_s[128];

    if (tid < 128) il_s[tid] = invsum[(size_t)z * T_ + m0 + tid];

    float4 acc[4][2];
#pragma unroll
    for (int i = 0; i < 4; i++)
#pragma unroll
        for (int j = 0; j < 2; j++) acc[i][j] = make_float4(0, 0, 0, 0);

    const int kmax = m0 + 128;
    for (int k0 = 0; k0 < kmax; k0 += 16) {
        __syncthreads();
        // A tile: normalized weights from raw scores; also write weights out.
#pragma unroll
        for (int it = 0; it < 2; it++) {
            int idx = tid + it * 256;
            int row = idx >> 2;
            int ko  = (idx & 3) << 2;
            float* addr = &Wz[(size_t)(m0 + row) * T_ + k0 + ko];
            float4 v = *(const float4*)addr;
            const int gm = m0 + row, gc = k0 + ko;
            const float il = il_s[row];
            float w0 = (gc     <= gm) ? exp2f(v.x * LOG2E) * il : 0.0f;
            float w1 = (gc + 1 <= gm) ? exp2f(v.y * LOG2E) * il : 0.0f;
            float w2 = (gc + 2 <= gm) ? exp2f(v.z * LOG2E) * il : 0.0f;
            float w3 = (gc + 3 <= gm) ? exp2f(v.w * LOG2E) * il : 0.0f;
            *(float4*)addr = make_float4(w0, w1, w2, w3);
            uint32_t hh;
            hh = f2tf(w0); Ah[row][ko + 0] = hh; Al[row][ko + 0] = f2tf(w0 - __uint_as_float(hh));
            hh = f2tf(w1); Ah[row][ko + 1] = hh; Al[row][ko + 1] = f2tf(w1 - __uint_as_float(hh));
            hh = f2tf(w2); Ah[row][ko + 2] = hh; Al[row][ko + 2] = f2tf(w2 - __uint_as_float(hh));
            hh = f2tf(w3); Ah[row][ko + 3] = hh; Al[row][ko + 3] = f2tf(w3 - __uint_as_float(hh));
        }
        // B tile: Bs[n][k] = V[k0+k][n]
        {
            int kr = tid >> 4;            // 0..15
            int nc = (tid & 15) << 2;     // 0..60
            float4 v = *(const float4*)(Vp + (size_t)(k0 + kr) * C_ + nc);
            uint32_t hh;
            hh = f2tf(v.x); Bh[nc + 0][kr] = hh; Bl[nc + 0][kr] = f2tf(v.x - __uint_as_float(hh));
            hh = f2tf(v.y); Bh[nc + 1][kr] = hh; Bl[nc + 1][kr] = f2tf(v.y - __uint_as_float(hh));
            hh = f2tf(v.z); Bh[nc + 2][kr] = hh; Bl[nc + 2][kr] = f2tf(v.z - __uint_as_float(hh));
            hh = f2tf(v.w); Bh[nc + 3][kr] = hh; Bl[nc + 3][kr] = f2tf(v.w - __uint_as_float(hh));
        }
        __syncthreads();
#pragma unroll
        for (int kb = 0; kb < 16; kb += 8) {
            uint32_t bh[2][2], bl[2][2];
#pragma unroll
            for (int nj = 0; nj < 2; nj++) {
                int col = wn + nj * 8 + r;
                bh[nj][0] = Bh[col][kb + c]; bh[nj][1] = Bh[col][kb + c + 4];
                bl[nj][0] = Bl[col][kb + c]; bl[nj][1] = Bl[col][kb + c + 4];
            }
#pragma unroll
            for (int mi = 0; mi < 4; mi++) {
                int row = wm + mi * 16 + r;
                uint32_t ah[4], al[4];
                ah[0] = Ah[row][kb + c];     ah[1] = Ah[row + 8][kb + c];
                ah[2] = Ah[row][kb + c + 4]; ah[3] = Ah[row + 8][kb + c + 4];
                al[0] = Al[row][kb + c];     al[1] = Al[row + 8][kb + c];
                al[2] = Al[row][kb + c + 4]; al[3] = Al[row + 8][kb + c + 4];
#pragma unroll
                for (int nj = 0; nj < 2; nj++) {
                    mma8(acc[mi][nj], al, bh[nj]);
                    mma8(acc[mi][nj], ah, bl[nj]);
                    mma8(acc[mi][nj], ah, bh[nj]);
                }
            }
        }
    }
#pragma unroll
    for (int mi = 0; mi < 4; mi++)
#pragma unroll
        for (int nj = 0; nj < 2; nj++) {
            int gm = m0 + wm + mi * 16 + r;
            int gn = wn + nj * 8 + 2 * c;
            *(float2*)&O[(size_t)(b * T_ + gm) * C_ + h * DH_ + gn] =
                make_float2(acc[mi][nj].x, acc[mi][nj].y);
            *(float2*)&O[(size_t)(b * T_ + gm + 8) * C_ + h * DH_ + gn] =
                make_float2(acc[mi][nj].z, acc[mi][nj].w);
        }
}

// ---------------------------------------------------------------------------
extern "C" void kernel_launch(void* const* d_in, const int* in_sizes, int n_in,
                              void* d_out, int out_size) {
    const float* x   = (const float*)d_in[0];
    const float* w_q = (const float*)d_in[1];
    const float* w_k = (const float*)d_in[2];
    const float* w_v = (const float*)d_in[3];
    const float* w_o = (const float*)d_in[4];

    float* qp; cudaGetSymbolAddress((void**)&qp, g_q);
    float* kp; cudaGetSymbolAddress((void**)&kp, g_k);
    float* vp; cudaGetSymbolAddress((void**)&vp, g_v);
    float* ap; cudaGetSymbolAddress((void**)&ap, g_att);
    float* pp; cudaGetSymbolAddress((void**)&pp, g_partial);
    float* ip; cudaGetSymbolAddress((void**)&ip, g_invsum);

    float* final_out = (float*)d_out;                       // [B,T,C]
    float* w_out = (float*)d_out + (size_t)B_ * T_ * C_;    // [B,H,T,T]

    const dim3 blk(256);

    gemm_qkv<<<dim3(18, 32), blk>>>(x, w_q, w_k, w_v, qp, kp, vp);

    scores_tc<<<dim3(T_ / 128, T_ / 128, B_ * H_), blk>>>(qp, kp, w_out, pp);

    reduce_kernel<<<(B_ * H_ * T_) / 256, blk>>>(pp, ip);

    pv_norm_tc<<<dim3(1, T_ / 128, B_ * H_), blk>>>(w_out, vp, ap, ip);

    gemm_final<<<dim3(6, 32), blk>>>(ap, w_o, final_out);
}

// round 5
// speedup vs baseline: 1.2087x; 1.0008x over previous
#include <cuda_runtime.h>
#include <math.h>
#include <stdint.h>

#define B_   2
#define T_   2048
#define C_   768
#define H_   12
#define DH_  64
#define LOG2E 1.4426950408889634f
#define SK   20   // smem k-stride (16 data + 4 pad) -> conflict-free frag LDS

// Scratch (device globals — no allocation allowed)
__device__ float g_q[B_ * T_ * C_];
__device__ float g_k[B_ * T_ * C_];
__device__ float g_v[B_ * T_ * C_];
__device__ float g_att[B_ * T_ * C_];
__device__ float g_partial[B_ * H_ * T_ * 16];  // per (row, colTile) partial sum(exp)
__device__ float g_invsum[B_ * H_ * T_];        // per row: 1/sum(exp)

// ---------------------------------------------------------------------------
// tf32 helpers
// ---------------------------------------------------------------------------
__device__ __forceinline__ uint32_t f2tf(float v) {
    uint32_t r;
    asm("cvt.rna.tf32.f32 %0, %1;" : "=r"(r) : "f"(v));
    return r;
}

__device__ __forceinline__ void mma8(float4& d, const uint32_t* a, const uint32_t* b) {
    asm("mma.sync.aligned.m16n8k8.row.col.f32.tf32.tf32.f32 "
        "{%0,%1,%2,%3}, {%4,%5,%6,%7}, {%8,%9}, {%0,%1,%2,%3};"
        : "+f"(d.x), "+f"(d.y), "+f"(d.z), "+f"(d.w)
        : "r"(a[0]), "r"(a[1]), "r"(a[2]), "r"(a[3]), "r"(b[0]), "r"(b[1]));
}

// Load a [128 rows x 16 k] fp32 tile (row stride ld) into hi/lo tf32 smem.
__device__ __forceinline__ void load_tile128(const float* __restrict__ src, int ld,
                                             uint32_t (*Sh)[SK], uint32_t (*Sl)[SK],
                                             int tid) {
#pragma unroll
    for (int it = 0; it < 2; it++) {
        int idx = tid + it * 256;            // 512 float4s total
        int row = idx >> 2;
        int ko  = (idx & 3) << 2;
        float4 v = *(const float4*)(src + (size_t)row * ld + ko);
        uint32_t h;
        h = f2tf(v.x); Sh[row][ko + 0] = h; Sl[row][ko + 0] = f2tf(v.x - __uint_as_float(h));
        h = f2tf(v.y); Sh[row][ko + 1] = h; Sl[row][ko + 1] = f2tf(v.y - __uint_as_float(h));
        h = f2tf(v.z); Sh[row][ko + 2] = h; Sl[row][ko + 2] = f2tf(v.z - __uint_as_float(h));
        h = f2tf(v.w); Sh[row][ko + 3] = h; Sl[row][ko + 3] = f2tf(v.w - __uint_as_float(h));
    }
}

// ---------------------------------------------------------------------------
// Shared NT-GEMM body (3xTF32). C[m,n] = sum_k A[m*lda+k]*B[n*ldb+k]
// ---------------------------------------------------------------------------
__device__ __forceinline__ void gemm_body(const float* __restrict__ A,
                                          const float* __restrict__ Bm,
                                          float* __restrict__ C,
                                          int K, int lda, int ldb, int ldc,
                                          int m0, int n0) {
    __shared__ uint32_t Ah[128][SK], Al[128][SK], Bh[128][SK], Bl[128][SK];
    const int tid = threadIdx.x;
    const int warp = tid >> 5, lane = tid & 31;
    const int wm = (warp >> 2) * 64, wn = (warp & 3) * 32;
    const int r = lane >> 2, c = lane & 3;

    float4 acc[4][4];
#pragma unroll
    for (int i = 0; i < 4; i++)
#pragma unroll
        for (int j = 0; j < 4; j++) acc[i][j] = make_float4(0, 0, 0, 0);

    for (int k0 = 0; k0 < K; k0 += 16) {
        __syncthreads();
        load_tile128(A + (size_t)m0 * lda + k0, lda, Ah, Al, tid);
        load_tile128(Bm + (size_t)n0 * ldb + k0, ldb, Bh, Bl, tid);
        __syncthreads();
#pragma unroll
        for (int kb = 0; kb < 16; kb += 8) {
            uint32_t bh[4][2], bl[4][2];
#pragma unroll
            for (int nj = 0; nj < 4; nj++) {
                int col = wn + nj * 8 + r;
                bh[nj][0] = Bh[col][kb + c]; bh[nj][1] = Bh[col][kb + c + 4];
                bl[nj][0] = Bl[col][kb + c]; bl[nj][1] = Bl[col][kb + c + 4];
            }
#pragma unroll
            for (int mi = 0; mi < 4; mi++) {
                int row = wm + mi * 16 + r;
                uint32_t ah[4], al[4];
                ah[0] = Ah[row][kb + c];     ah[1] = Ah[row + 8][kb + c];
                ah[2] = Ah[row][kb + c + 4]; ah[3] = Ah[row + 8][kb + c + 4];
                al[0] = Al[row][kb + c];     al[1] = Al[row + 8][kb + c];
                al[2] = Al[row][kb + c + 4]; al[3] = Al[row + 8][kb + c + 4];
#pragma unroll
                for (int nj = 0; nj < 4; nj++) {
                    mma8(acc[mi][nj], al, bh[nj]);
                    mma8(acc[mi][nj], ah, bl[nj]);
                    mma8(acc[mi][nj], ah, bh[nj]);
                }
            }
        }
    }
#pragma unroll
    for (int mi = 0; mi < 4; mi++)
#pragma unroll
        for (int nj = 0; nj < 4; nj++) {
            int gm = m0 + wm + mi * 16 + r;
            int gn = n0 + wn + nj * 8 + 2 * c;
            *(float2*)&C[(size_t)gm * ldc + gn]       = make_float2(acc[mi][nj].x, acc[mi][nj].y);
            *(float2*)&C[(size_t)(gm + 8) * ldc + gn] = make_float2(acc[mi][nj].z, acc[mi][nj].w);
        }
}

// Fused QKV projection: grid (18, 32); x-blocks [0,6)->Q, [6,12)->K, [12,18)->V
__global__ void __launch_bounds__(256) gemm_qkv(const float* __restrict__ x,
                                                const float* __restrict__ wq,
                                                const float* __restrict__ wk,
                                                const float* __restrict__ wv,
                                                float* __restrict__ q,
                                                float* __restrict__ k,
                                                float* __restrict__ v) {
    const int nb = blockIdx.x;
    const int sel = nb / 6;
    const int n0 = (nb % 6) * 128;
    const int m0 = blockIdx.y * 128;
    const float* W = (sel == 0) ? wq : (sel == 1) ? wk : wv;
    float* O = (sel == 0) ? q : (sel == 1) ? k : v;
    gemm_body(x, W, O, C_, C_, C_, C_, m0, n0);
}

// Final projection: grid (6, 32)
__global__ void __launch_bounds__(256) gemm_final(const float* __restrict__ A,
                                                  const float* __restrict__ Wo,
                                                  float* __restrict__ C) {
    gemm_body(A, Wo, C, C_, C_, C_, C_, blockIdx.y * 128, blockIdx.x * 128);
}

// ---------------------------------------------------------------------------
// Scores + per-tile row partial sums of exp.
// S = 0.125*Q.K^T (masked->0). partial[(z*T+row)*16 + n0/128] = sum_j exp(S)
// grid (16, 16, 24)
// ---------------------------------------------------------------------------
__global__ void __launch_bounds__(256) scores_tc(const float* __restrict__ Q,
                                                 const float* __restrict__ Kt,
                                                 float* __restrict__ W,
                                                 float* __restrict__ partial) {
    const int z = blockIdx.z;
    const int b = z / H_, h = z % H_;
    const int m0 = blockIdx.y * 128, n0 = blockIdx.x * 128;
    const int tid = threadIdx.x;
    float* Cz = W + (size_t)z * T_ * T_;

    if (n0 > m0) {  // fully masked tile -> zeros; no partials
        const float4 zz = make_float4(0, 0, 0, 0);
        for (int idx = tid; idx < 128 * 32; idx += 256) {
            int row = idx >> 5, c4 = (idx & 31) << 2;
            *(float4*)&Cz[(size_t)(m0 + row) * T_ + n0 + c4] = zz;
        }
        return;
    }

    __shared__ uint32_t Ah[128][SK], Al[128][SK], Bh[128][SK], Bl[128][SK];
    __shared__ float spart[128][4];
    const int warp = tid >> 5, lane = tid & 31;
    const int wm = (warp >> 2) * 64, wn = (warp & 3) * 32;
    const int r = lane >> 2, c = lane & 3;
    const float* Ap = Q + (size_t)b * T_ * C_ + h * DH_;
    const float* Bp = Kt + (size_t)b * T_ * C_ + h * DH_;

    float4 acc[4][4];
#pragma unroll
    for (int i = 0; i < 4; i++)
#pragma unroll
        for (int j = 0; j < 4; j++) acc[i][j] = make_float4(0, 0, 0, 0);

#pragma unroll
    for (int k0 = 0; k0 < DH_; k0 += 16) {
        __syncthreads();
        load_tile128(Ap + (size_t)m0 * C_ + k0, C_, Ah, Al, tid);
        load_tile128(Bp + (size_t)n0 * C_ + k0, C_, Bh, Bl, tid);
        __syncthreads();
#pragma unroll
        for (int kb = 0; kb < 16; kb += 8) {
            uint32_t bh[4][2], bl[4][2];
#pragma unroll
            for (int nj = 0; nj < 4; nj++) {
                int col = wn + nj * 8 + r;
                bh[nj][0] = Bh[col][kb + c]; bh[nj][1] = Bh[col][kb + c + 4];
                bl[nj][0] = Bl[col][kb + c]; bl[nj][1] = Bl[col][kb + c + 4];
            }
#pragma unroll
            for (int mi = 0; mi < 4; mi++) {
                int row = wm + mi * 16 + r;
                uint32_t ah[4], al[4];
                ah[0] = Ah[row][kb + c];     ah[1] = Ah[row + 8][kb + c];
                ah[2] = Ah[row][kb + c + 4]; ah[3] = Ah[row + 8][kb + c + 4];
                al[0] = Al[row][kb + c];     al[1] = Al[row + 8][kb + c];
                al[2] = Al[row][kb + c + 4]; al[3] = Al[row + 8][kb + c + 4];
#pragma unroll
                for (int nj = 0; nj < 4; nj++) {
                    mma8(acc[mi][nj], al, bh[nj]);
                    mma8(acc[mi][nj], ah, bl[nj]);
                    mma8(acc[mi][nj], ah, bh[nj]);
                }
            }
        }
    }

    const bool diag = (n0 == m0);
#pragma unroll
    for (int mi = 0; mi < 4; mi++) {
        float se0 = 0.0f, se1 = 0.0f;   // exp-sums for rows gm and gm+8
        int gm = m0 + wm + mi * 16 + r;
#pragma unroll
        for (int nj = 0; nj < 4; nj++) {
            int gn = n0 + wn + nj * 8 + 2 * c;
            float x0 = 0.125f * acc[mi][nj].x, y0 = 0.125f * acc[mi][nj].y;
            float z1 = 0.125f * acc[mi][nj].z, w1 = 0.125f * acc[mi][nj].w;
            bool vx = true, vy = true, vz = true, vw = true;
            if (diag) {
                vx = (gn <= gm); vy = (gn + 1 <= gm);
                vz = (gn <= gm + 8); vw = (gn + 1 <= gm + 8);
                if (!vx) x0 = 0.0f;
                if (!vy) y0 = 0.0f;
                if (!vz) z1 = 0.0f;
                if (!vw) w1 = 0.0f;
            }
            se0 += (vx ? exp2f(x0 * LOG2E) : 0.0f) + (vy ? exp2f(y0 * LOG2E) : 0.0f);
            se1 += (vz ? exp2f(z1 * LOG2E) : 0.0f) + (vw ? exp2f(w1 * LOG2E) : 0.0f);
            *(float2*)&Cz[(size_t)gm * T_ + gn]       = make_float2(x0, y0);
            *(float2*)&Cz[(size_t)(gm + 8) * T_ + gn] = make_float2(z1, w1);
        }
        // reduce over the 4 c-lanes (lane bits 0-1)
        se0 += __shfl_xor_sync(0xffffffffu, se0, 1);
        se0 += __shfl_xor_sync(0xffffffffu, se0, 2);
        se1 += __shfl_xor_sync(0xffffffffu, se1, 1);
        se1 += __shfl_xor_sync(0xffffffffu, se1, 2);
        if (c == 0) {
            spart[wm + mi * 16 + r][warp & 3]     = se0;
            spart[wm + mi * 16 + r + 8][warp & 3] = se1;
        }
    }
    __syncthreads();
    if (tid < 128) {
        float s = spart[tid][0] + spart[tid][1] + spart[tid][2] + spart[tid][3];
        partial[((size_t)z * T_ + m0 + tid) * 16 + (n0 >> 7)] = s;
    }
}

// ---------------------------------------------------------------------------
// Reduce partials -> 1/rowsum. grid (B*H*T/256), 256 thr.
// ---------------------------------------------------------------------------
__global__ void __launch_bounds__(256) reduce_kernel(const float* __restrict__ partial,
                                                     float* __restrict__ invsum) {
    const int rg = blockIdx.x * 256 + threadIdx.x;   // [0, B*H*T)
    const int i = rg % T_;
    const int ntmax = i >> 7;
    float s = 0.0f;
    const float* p = partial + (size_t)rg * 16;
    for (int nt = 0; nt <= ntmax; nt++) s += p[nt];
    invsum[rg] = 1.0f / s;
}

// ---------------------------------------------------------------------------
// Fused normalize + weights-write + PV (3xTF32):
//   w = exp(s)*invsum (masked->0), write w, O = w @ V.
// grid (1, 16, 24), y reversed for wave balance.
// ---------------------------------------------------------------------------
__global__ void __launch_bounds__(256) pv_norm_tc(float* __restrict__ W,
                                                  const float* __restrict__ V,
                                                  float* __restrict__ O,
                                                  const float* __restrict__ invsum) {
    const int z = blockIdx.z;
    const int b = z / H_, h = z % H_;
    const int m0 = (gridDim.y - 1 - blockIdx.y) * 128;   // heavy blocks first
    const int tid = threadIdx.x;
    const int warp = tid >> 5, lane = tid & 31;
    const int wm = (warp >> 2) * 64, wn = (warp & 3) * 16;
    const int r = lane >> 2, c = lane & 3;

    float* Wz = W + (size_t)z * T_ * T_;
    const float* Vp = V + (size_t)b * T_ * C_ + h * DH_;   // V[k][n], stride C_

    __shared__ uint32_t Ah[128][SK], Al[128][SK], Bh[64][SK], Bl[64][SK];
    __shared__ float il_s[128];

    if (tid < 128) il_s[tid] = invsum[(size_t)z * T_ + m0 + tid];

    float4 acc[4][2];
#pragma unroll
    for (int i = 0; i < 4; i++)
#pragma unroll
        for (int j = 0; j < 2; j++) acc[i][j] = make_float4(0, 0, 0, 0);

    const int kmax = m0 + 128;
    for (int k0 = 0; k0 < kmax; k0 += 16) {
        __syncthreads();
        // A tile: normalized weights from raw scores; also write weights out.
#pragma unroll
        for (int it = 0; it < 2; it++) {
            int idx = tid + it * 256;
            int row = idx >> 2;
            int ko  = (idx & 3) << 2;
            float* addr = &Wz[(size_t)(m0 + row) * T_ + k0 + ko];
            float4 v = *(const float4*)addr;
            const int gm = m0 + row, gc = k0 + ko;
            const float il = il_s[row];
            float w0 = (gc     <= gm) ? exp2f(v.x * LOG2E) * il : 0.0f;
            float w1 = (gc + 1 <= gm) ? exp2f(v.y * LOG2E) * il : 0.0f;
            float w2 = (gc + 2 <= gm) ? exp2f(v.z * LOG2E) * il : 0.0f;
            float w3 = (gc + 3 <= gm) ? exp2f(v.w * LOG2E) * il : 0.0f;
            *(float4*)addr = make_float4(w0, w1, w2, w3);
            uint32_t hh;
            hh = f2tf(w0); Ah[row][ko + 0] = hh; Al[row][ko + 0] = f2tf(w0 - __uint_as_float(hh));
            hh = f2tf(w1); Ah[row][ko + 1] = hh; Al[row][ko + 1] = f2tf(w1 - __uint_as_float(hh));
            hh = f2tf(w2); Ah[row][ko + 2] = hh; Al[row][ko + 2] = f2tf(w2 - __uint_as_float(hh));
            hh = f2tf(w3); Ah[row][ko + 3] = hh; Al[row][ko + 3] = f2tf(w3 - __uint_as_float(hh));
        }
        // B tile: Bs[n][k] = V[k0+k][n]
        {
            int kr = tid >> 4;            // 0..15
            int nc = (tid & 15) << 2;     // 0..60
            float4 v = *(const float4*)(Vp + (size_t)(k0 + kr) * C_ + nc);
            uint32_t hh;
            hh = f2tf(v.x); Bh[nc + 0][kr] = hh; Bl[nc + 0][kr] = f2tf(v.x - __uint_as_float(hh));
            hh = f2tf(v.y); Bh[nc + 1][kr] = hh; Bl[nc + 1][kr] = f2tf(v.y - __uint_as_float(hh));
            hh = f2tf(v.z); Bh[nc + 2][kr] = hh; Bl[nc + 2][kr] = f2tf(v.z - __uint_as_float(hh));
            hh = f2tf(v.w); Bh[nc + 3][kr] = hh; Bl[nc + 3][kr] = f2tf(v.w - __uint_as_float(hh));
        }
        __syncthreads();
#pragma unroll
        for (int kb = 0; kb < 16; kb += 8) {
            uint32_t bh[2][2], bl[2][2];
#pragma unroll
            for (int nj = 0; nj < 2; nj++) {
                int col = wn + nj * 8 + r;
                bh[nj][0] = Bh[col][kb + c]; bh[nj][1] = Bh[col][kb + c + 4];
                bl[nj][0] = Bl[col][kb + c]; bl[nj][1] = Bl[col][kb + c + 4];
            }
#pragma unroll
            for (int mi = 0; mi < 4; mi++) {
                int row = wm + mi * 16 + r;
                uint32_t ah[4], al[4];
                ah[0] = Ah[row][kb + c];     ah[1] = Ah[row + 8][kb + c];
                ah[2] = Ah[row][kb + c + 4]; ah[3] = Ah[row + 8][kb + c + 4];
                al[0] = Al[row][kb + c];     al[1] = Al[row + 8][kb + c];
                al[2] = Al[row][kb + c + 4]; al[3] = Al[row + 8][kb + c + 4];
#pragma unroll
                for (int nj = 0; nj < 2; nj++) {
                    mma8(acc[mi][nj], al, bh[nj]);
                    mma8(acc[mi][nj], ah, bl[nj]);
                    mma8(acc[mi][nj], ah, bh[nj]);
                }
            }
        }
    }
#pragma unroll
    for (int mi = 0; mi < 4; mi++)
#pragma unroll
        for (int nj = 0; nj < 2; nj++) {
            int gm = m0 + wm + mi * 16 + r;
            int gn = wn + nj * 8 + 2 * c;
            *(float2*)&O[(size_t)(b * T_ + gm) * C_ + h * DH_ + gn] =
                make_float2(acc[mi][nj].x, acc[mi][nj].y);
            *(float2*)&O[(size_t)(b * T_ + gm + 8) * C_ + h * DH_ + gn] =
                make_float2(acc[mi][nj].z, acc[mi][nj].w);
        }
}

// ---------------------------------------------------------------------------
extern "C" void kernel_launch(void* const* d_in, const int* in_sizes, int n_in,
                              void* d_out, int out_size) {
    const float* x   = (const float*)d_in[0];
    const float* w_q = (const float*)d_in[1];
    const float* w_k = (const float*)d_in[2];
    const float* w_v = (const float*)d_in[3];
    const float* w_o = (const float*)d_in[4];

    float* qp; cudaGetSymbolAddress((void**)&qp, g_q);
    float* kp; cudaGetSymbolAddress((void**)&kp, g_k);
    float* vp; cudaGetSymbolAddress((void**)&vp, g_v);
    float* ap; cudaGetSymbolAddress((void**)&ap, g_att);
    float* pp; cudaGetSymbolAddress((void**)&pp, g_partial);
    float* ip; cudaGetSymbolAddress((void**)&ip, g_invsum);

    float* final_out = (float*)d_out;                       // [B,T,C]
    float* w_out = (float*)d_out + (size_t)B_ * T_ * C_;    // [B,H,T,T]

    const dim3 blk(256);

    gemm_qkv<<<dim3(18, 32), blk>>>(x, w_q, w_k, w_v, qp, kp, vp);

    scores_tc<<<dim3(T_ / 128, T_ / 128, B_ * H_), blk>>>(qp, kp, w_out, pp);

    reduce_kernel<<<(B_ * H_ * T_) / 256, blk>>>(pp, ip);

    pv_norm_tc<<<dim3(1, T_ / 128, B_ * H_), blk>>>(w_out, vp, ap, ip);

    gemm_final<<<dim3(6, 32), blk>>>(ap, w_o, final_out);
}